// round 16
// baseline (speedup 1.0000x reference)
#include <cuda_runtime.h>
#include <math.h>

#define GRID 296
#define TT 12
#define DD 128
#define NPL (1536 * 512)
#define MSZ (512 * 512)
#define EPSBN 1e-5f

__device__ __align__(16) float g_Y0[NPL];
__device__ __align__(16) float g_Ys[2 * NPL];     // solid Y1, Y2
__device__ __align__(16) float g_Hp[6 * NPL];     // 3 K-parts x 2 planes
__device__ __align__(16) float g_A2[MSZ];
__device__ __align__(16) float g_A2p[2 * MSZ];
__device__ __align__(16) float g_q[5 * 512];
__device__ float g_Sfin[10 * DD];
__device__ float g_SkUf[DD * 5];
__device__ float g_mo[DD];
__device__ unsigned g_bcnt = 0u;
__device__ unsigned g_bgen = 0u;

typedef unsigned long long ull;
union F2U { ull u; float2 f; };
__device__ __forceinline__ ull pack2(float x, float y) {
    ull r; asm("mov.b64 %0, {%1, %2};" : "=l"(r) : "f"(x), "f"(y)); return r;
}
__device__ __forceinline__ void fma2(ull& d, ull a, ull b) {
    asm("fma.rn.f32x2 %0, %1, %2, %3;" : "=l"(d) : "l"(a), "l"(b), "l"(d));
}

__device__ __forceinline__ void grid_sync() {
    __threadfence();
    __syncthreads();
    if (threadIdx.x == 0) {
        unsigned gen = atomicAdd(&g_bgen, 0u);
        if (atomicAdd(&g_bcnt, 1u) == (unsigned)GRID - 1u) {
            atomicExch(&g_bcnt, 0u);
            __threadfence();
            atomicAdd(&g_bgen, 1u);
        } else {
            while (atomicAdd(&g_bgen, 0u) == gen) __nanosleep(128);
        }
        __threadfence();
    }
    __syncthreads();
}

// ------- 128x128 SGEMM tile, 8x8/thread, FFMA2 inner loop ----
__device__ __forceinline__ void sgemm128(float* SMb,
    const float* __restrict__ A, const float* __restrict__ B, float* __restrict__ C,
    int m0, int n0, int k0, int nkt)
{
    float (*As)[128] = (float(*)[128])SMb;            // As[k][m]
    float (*Bs)[128] = (float(*)[128])(SMb + 2048);   // Bs[k][n]
    int tid = threadIdx.x;
    int tx = tid & 15, ty = tid >> 4;
    int ar0 = tid >> 1, ak0 = (tid & 1) << 3;
    const float* Ap = A + (size_t)(m0 + ar0) * 512 + k0 + ak0;
    int bk = tid >> 5, bc = (tid & 31) << 2;
    const float* Bp0 = B + (size_t)(k0 + bk) * 512 + n0 + bc;
    const float* Bp1 = Bp0 + (size_t)8 * 512;

    float4 a0 = *(const float4*)Ap;
    float4 a1 = *(const float4*)(Ap + 4);
    float4 b0 = *(const float4*)Bp0;
    float4 b1 = *(const float4*)Bp1;

    ull acc[8][4];
#pragma unroll
    for (int i = 0; i < 8; i++)
#pragma unroll
        for (int j = 0; j < 4; j++) acc[i][j] = 0ull;

#pragma unroll 1
    for (int kt = 0; kt < nkt; kt++) {
        As[ak0 + 0][ar0] = a0.x; As[ak0 + 1][ar0] = a0.y;
        As[ak0 + 2][ar0] = a0.z; As[ak0 + 3][ar0] = a0.w;
        As[ak0 + 4][ar0] = a1.x; As[ak0 + 5][ar0] = a1.y;
        As[ak0 + 6][ar0] = a1.z; As[ak0 + 7][ar0] = a1.w;
        *(float4*)&Bs[bk][bc] = b0;
        *(float4*)&Bs[bk + 8][bc] = b1;
        __syncthreads();
        if (kt + 1 < nkt) {
            a0 = *(const float4*)(Ap + (kt + 1) * 16);
            a1 = *(const float4*)(Ap + (kt + 1) * 16 + 4);
            b0 = *(const float4*)(Bp0 + (size_t)(kt + 1) * 16 * 512);
            b1 = *(const float4*)(Bp1 + (size_t)(kt + 1) * 16 * 512);
        }
#pragma unroll
        for (int k = 0; k < 16; k++) {
            float a[8];
            *(float4*)&a[0] = *(const float4*)&As[k][ty * 8];
            *(float4*)&a[4] = *(const float4*)&As[k][ty * 8 + 4];
            ulonglong2 bA = *(const ulonglong2*)&Bs[k][tx * 8];
            ulonglong2 bB = *(const ulonglong2*)&Bs[k][tx * 8 + 4];
#pragma unroll
            for (int i = 0; i < 8; i++) {
                ull ap = pack2(a[i], a[i]);
                fma2(acc[i][0], ap, (ull)bA.x);
                fma2(acc[i][1], ap, (ull)bA.y);
                fma2(acc[i][2], ap, (ull)bB.x);
                fma2(acc[i][3], ap, (ull)bB.y);
            }
        }
        __syncthreads();
    }
#pragma unroll
    for (int i = 0; i < 8; i++) {
        F2U u0, u1, u2, u3;
        u0.u = acc[i][0]; u1.u = acc[i][1]; u2.u = acc[i][2]; u3.u = acc[i][3];
        float* cp = C + (size_t)(m0 + ty * 8 + i) * 512 + n0 + tx * 8;
        *(float4*)cp = make_float4(u0.f.x, u0.f.y, u1.f.x, u1.f.y);
        *(float4*)(cp + 4) = make_float4(u2.f.x, u2.f.y, u3.f.x, u3.f.y);
    }
}

// ------------- colsum / vecmat (64 cols per task) -------------
__device__ void colsum_task(float* SMf, const float* __restrict__ M, float* dst, int blk) {
    int tid = threadIdx.x;
    int col = blk * 64 + (tid & 63);
    int rs = tid >> 6;
    float a = 0.f;
#pragma unroll 8
    for (int v = rs * 128; v < rs * 128 + 128; v++) a += M[(size_t)v * 512 + col];
    SMf[tid] = a;
    __syncthreads();
    if (rs == 0)
        dst[col] = SMf[tid] + SMf[tid + 64] + SMf[tid + 128] + SMf[tid + 192];
}
__device__ void vecmat_task(float* SMf, const float* __restrict__ qsrc,
                            const float* __restrict__ M, float* dst, int blk) {
    int tid = threadIdx.x;
    for (int i = tid; i < 512; i += 256) SMf[i] = qsrc[i];
    __syncthreads();
    int col = blk * 64 + (tid & 63);
    int rs = tid >> 6;
    float a = 0.f;
#pragma unroll 8
    for (int v = rs * 128; v < rs * 128 + 128; v++) a += SMf[v] * M[(size_t)v * 512 + col];
    SMf[512 + tid] = a;
    __syncthreads();
    if (rs == 0)
        dst[col] = SMf[512 + tid] + SMf[512 + tid + 64]
                 + SMf[512 + tid + 128] + SMf[512 + tid + 192];
}

// ------------- warp-cooperative composite chain ---------
__device__ void composite_run(float* SM,
    const float* __restrict__ W_start, const float* __restrict__ b_start,
    const float* __restrict__ W_skip,  const float* __restrict__ b_skip,
    const float* __restrict__ W_gc,    const float* __restrict__ b_gc,
    const float* __restrict__ gcg, const float* __restrict__ gcb,
    const float* __restrict__ gcm, const float* __restrict__ gcv,
    const float* __restrict__ bng, const float* __restrict__ bnb,
    const float* __restrict__ bnm, const float* __restrict__ bnv,
    const float* __restrict__ obg, const float* __restrict__ obb,
    const float* __restrict__ obm, const float* __restrict__ obv)
{
    float* Sg  = SM;
    float* Ca  = SM + 5760;
    float* Ua  = Ca + 1280;
    float* SkC = Ua + 640;
    float* SkU = SkC + 1280;
    int tid = threadIdx.x, wid = tid >> 5, lane = tid & 31;

    for (int i = tid; i < 1280; i += 256) { Ca[i] = 0.f; SkC[i] = 0.f; }
    for (int i = tid; i < 640;  i += 256) { Ua[i] = 0.f; SkU[i] = 0.f; }
    __syncthreads();
    if (tid < 128) {
        Ca[tid * 2 + 0] = W_start[tid * 2 + 0];
        Ca[tid * 2 + 1] = W_start[tid * 2 + 1];
        Ua[tid * 5] = b_start[tid];
    }
    __syncthreads();
    for (int s = 0; s < 5; s++) {
        int i = s >> 1, isgc = s & 1;
        int jmax = isgc ? 384 : 128;
        for (int j = tid; j < jmax; j += 256) {
            int sub = j >> 7, m = j & 127;
#pragma unroll
            for (int v = 0; v < 10; v++) {
                int p = (v >> 1) - sub;
                Sg[j * 15 + v] = (p >= 0) ? Ca[p * 256 + m * 2 + (v & 1)] : 0.f;
            }
#pragma unroll
            for (int k = 0; k < 5; k++) {
                int kk = k - sub;
                Sg[j * 15 + 10 + k] = (kk >= 0) ? Ua[m * 5 + kk] : 0.f;
            }
        }
        __syncthreads();
        const float* Wb = isgc ? (W_gc + i * 128 * 384) : (W_skip + i * 128 * 128);
        for (int ci = 0; ci < 16; ci++) {
            int c = wid * 16 + ci;
            const float* Wr = Wb + (size_t)c * jmax;
            float acc[15];
#pragma unroll
            for (int v = 0; v < 15; v++) acc[v] = 0.f;
            int nu = isgc ? 12 : 4;
            for (int u = 0; u < nu; u++) {
                float w = Wr[lane + u * 32];
                const float* sp = &Sg[(lane + u * 32) * 15];
#pragma unroll
                for (int v = 0; v < 15; v++) acc[v] += w * sp[v];
            }
            float mine = 0.f;
#pragma unroll
            for (int v = 0; v < 15; v++) {
                float r = acc[v];
#pragma unroll
                for (int o = 16; o; o >>= 1) r += __shfl_xor_sync(0xffffffffu, r, o);
                if (lane == v) mine = r;
            }
            if (!isgc) {
                if (lane < 10) SkC[(lane >> 1) * 256 + c * 2 + (lane & 1)] += mine;
                else if (lane < 15) {
                    int kk = lane - 10;
                    SkU[c * 5 + kk] += mine + ((kk == 0) ? b_skip[i * 128 + c] : 0.f);
                }
            } else if (lane < 15) {
                float ig = gcg[i * 128 + c] * rsqrtf(gcv[i * 128 + c] + EPSBN);
                float mg = gcb[i * 128 + c] - gcm[i * 128 + c] * ig;
                float ib = bng[i * 128 + c] * rsqrtf(bnv[i * 128 + c] + EPSBN);
                float mb = bnb[i * 128 + c] - bnm[i * 128 + c] * ib;
                if (lane < 10) {
                    int p = lane >> 1, e = lane & 1, id = p * 256 + c * 2 + e;
                    Ca[id] = ib * (ig * mine + Ca[id]);
                } else {
                    int kk = lane - 10, id = c * 5 + kk;
                    float h = mine + ((kk == 0) ? b_gc[i * 128 + c] : 0.f);
                    Ua[id] = ib * (ig * h + ((kk == 0) ? mg : 0.f) + Ua[id])
                           + ((kk == 0) ? mb : 0.f);
                }
            }
        }
        __syncthreads();
    }
    if (tid < 128) {
        int c = tid;
        float io = obg[c] * rsqrtf(obv[c] + EPSBN);
#pragma unroll
        for (int v = 0; v < 10; v++)
            g_Sfin[v * 128 + c] = io * SkC[(v >> 1) * 256 + c * 2 + (v & 1)];
#pragma unroll
        for (int k = 0; k < 5; k++) g_SkUf[c * 5 + k] = io * SkU[c * 5 + k];
        g_mo[c] = obb[c] - obm[c] * io;
    }
}

// ---------------- the single persistent kernel ----------------
__global__ void __launch_bounds__(256, 2) k_mega(
    const float* __restrict__ x, const float* __restrict__ adj,
    const float* __restrict__ W_start, const float* __restrict__ b_start,
    const float* __restrict__ W_skip,  const float* __restrict__ b_skip,
    const float* __restrict__ W_gc,    const float* __restrict__ b_gc,
    const float* __restrict__ gcg, const float* __restrict__ gcb,
    const float* __restrict__ gcm, const float* __restrict__ gcv,
    const float* __restrict__ bng, const float* __restrict__ bnb,
    const float* __restrict__ bnm, const float* __restrict__ bnv,
    const float* __restrict__ obg, const float* __restrict__ obb,
    const float* __restrict__ obm, const float* __restrict__ obv,
    float* __restrict__ out)
{
    __shared__ __align__(16) float SM[9600];
    int bid = blockIdx.x, tid = threadIdx.x;

    // ===== P0: transpose(128) | A^2 split-2 (32) | q1(8) | composite(1) =====
    for (int t = bid; t < 169; t += GRID) {
        __syncthreads();
        if (t < 128) {
            const float* src = x + (size_t)t * 6144;
            for (int i = tid; i < 6144; i += 256) SM[i] = src[i];
            __syncthreads();
            float* dst = g_Y0 + (size_t)t * 6144;
            for (int i = tid; i < 6144; i += 256) {
                int tt = i >> 9, n = i & 511;
                dst[i] = SM[n * TT + tt];
            }
        } else if (t < 160) {
            int ti = t - 128, kh = ti >> 4, tile = ti & 15;
            sgemm128(SM, adj, adj, g_A2p + (size_t)kh * MSZ,
                     (tile >> 2) * 128, (tile & 3) * 128, kh * 256, 16);
        } else if (t < 168) {
            colsum_task(SM, adj, g_q + 512, t - 160);
        } else {
            composite_run(SM, W_start, b_start, W_skip, b_skip, W_gc, b_gc,
                          gcg, gcb, gcm, gcv, bng, bnb, bnm, bnv,
                          obg, obb, obm, obv);
        }
    }
    grid_sync();

    // ===== P0b: solidify A^2 (16 tasks) =====
    for (int t = bid; t < 16; t += GRID) {
        const float4* pa = (const float4*)g_A2p + (size_t)t * 4096;
        const float4* pb = pa + MSZ / 4;
        float4* pd = (float4*)g_A2 + (size_t)t * 4096;
        for (int i = tid; i < 4096; i += 256) {
            float4 a = pa[i], b = pb[i];
            pd[i] = make_float4(a.x + b.x, a.y + b.y, a.z + b.z, a.w + b.w);
        }
    }
    grid_sync();

    // ===== P1: Y1 thirds(144) | Y2 thirds(144) | q2(8) = 296 =====
    for (int t = bid; t < 296; t += GRID) {
        __syncthreads();
        if (t < 288) {
            int plane = t / 144, r = t % 144;
            int kh = r / 48, rr = r % 48;
            sgemm128(SM, g_Y0, plane ? g_A2 : adj,
                     g_Hp + (size_t)kh * (2 * NPL) + (size_t)plane * NPL,
                     (rr >> 2) * 128, (rr & 3) * 128, kh * 176, (kh == 2) ? 10 : 11);
        } else {
            colsum_task(SM, g_A2, g_q + 1024, t - 288);
        }
    }
    grid_sync();

    // ===== P1b: solidify Y1,Y2 (48) | q3(8) | q4(8) = 64 =====
    for (int t = bid; t < 64; t += GRID) {
        __syncthreads();
        if (t < 48) {
            const float4* p0 = (const float4*)g_Hp + (size_t)t * 8192;
            const float4* p1 = p0 + (2 * NPL) / 4;
            const float4* p2 = p1 + (2 * NPL) / 4;
            float4* pd = (float4*)g_Ys + (size_t)t * 8192;
            for (int i = tid; i < 8192; i += 256) {
                float4 a = p0[i], b = p1[i], c = p2[i];
                pd[i] = make_float4(a.x + b.x + c.x, a.y + b.y + c.y,
                                    a.z + b.z + c.z, a.w + b.w + c.w);
            }
        } else if (t < 56) {
            vecmat_task(SM, g_q + 512, g_A2, g_q + 1536, t - 48);
        } else {
            vecmat_task(SM, g_q + 1024, g_A2, g_q + 2048, t - 56);
        }
    }
    grid_sync();

    // ===== P2: Y3 thirds(144) | Y4 thirds(144) = 288 =====
    for (int t = bid; t < 288; t += GRID) {
        __syncthreads();
        int plane = t / 144, r = t % 144;
        int kh = r / 48, rr = r % 48;
        sgemm128(SM, g_Ys + (size_t)plane * NPL, g_A2,
                 g_Hp + (size_t)kh * (2 * NPL) + (size_t)plane * NPL,
                 (rr >> 2) * 128, (rr & 3) * 128, kh * 176, (kh == 2) ? 10 : 11);
    }
    grid_sync();

    // ===== P3: final expansion (12288 tiles of 32 nodes) =====
    {
        float* S    = SM;            // 1280
        float* SkUs = SM + 1280;     // 640
        float* mos  = SM + 1920;     // 128
        float* qs   = SM + 2048;     // 2048
        for (int i = tid; i < 1280; i += 256) S[i] = g_Sfin[i];
        for (int i = tid; i < 640;  i += 256) SkUs[i] = g_SkUf[i];
        if (tid < 128) mos[tid] = g_mo[tid];
        for (int i = tid; i < 2048; i += 256) qs[i] = g_q[512 + i];
        __syncthreads();
        int i = tid >> 3, c0 = (tid & 7) * 16;
        for (int task = bid; task < 12288; task += GRID) {
            int nt = task & 15, bt = task >> 4;
            int b = bt / TT, tt = bt - b * TT;
            int n = nt * 32 + i;
            size_t ro = (size_t)((b * 2) * TT + tt) * 512 + n;
            size_t r1 = ro + (size_t)TT * 512;
            float y[10];
            y[0] = g_Y0[ro]; y[1] = g_Y0[r1];
            y[2] = g_Ys[ro]; y[3] = g_Ys[r1];
            y[4] = g_Ys[NPL + ro]; y[5] = g_Ys[NPL + r1];
            y[6] = g_Hp[ro] + g_Hp[2 * NPL + ro] + g_Hp[4 * NPL + ro];
            y[7] = g_Hp[r1] + g_Hp[2 * NPL + r1] + g_Hp[4 * NPL + r1];
            y[8] = g_Hp[NPL + ro] + g_Hp[3 * NPL + ro] + g_Hp[5 * NPL + ro];
            y[9] = g_Hp[NPL + r1] + g_Hp[3 * NPL + r1] + g_Hp[5 * NPL + r1];
            float q1 = qs[n], q2 = qs[512 + n], q3 = qs[1024 + n], q4 = qs[1536 + n];
            float acc[16];
#pragma unroll
            for (int cc = 0; cc < 16; cc++) {
                int c = c0 + cc;
                acc[cc] = mos[c] + SkUs[c * 5 + 0] + SkUs[c * 5 + 1] * q1
                        + SkUs[c * 5 + 2] * q2 + SkUs[c * 5 + 3] * q3
                        + SkUs[c * 5 + 4] * q4;
            }
#pragma unroll
            for (int j = 0; j < 10; j++) {
                float yj = y[j];
#pragma unroll
                for (int cc = 0; cc < 16; cc++) acc[cc] += yj * S[j * 128 + c0 + cc];
            }
            float* op = out + (size_t)(bt * 512 + n) * 128 + c0;
#pragma unroll
            for (int q4i = 0; q4i < 4; q4i++)
                *(float4*)(op + q4i * 4) = make_float4(acc[q4i * 4], acc[q4i * 4 + 1],
                                                       acc[q4i * 4 + 2], acc[q4i * 4 + 3]);
        }
    }
}

extern "C" void kernel_launch(void* const* d_in, const int* in_sizes, int n_in,
                              void* d_out, int out_size) {
    const float* x       = (const float*)d_in[0];
    const float* adj     = (const float*)d_in[1];
    const float* W_start = (const float*)d_in[2];
    const float* b_start = (const float*)d_in[3];
    const float* W_skip  = (const float*)d_in[4];
    const float* b_skip  = (const float*)d_in[5];
    const float* W_gc    = (const float*)d_in[6];
    const float* b_gc    = (const float*)d_in[7];
    const float* gcg     = (const float*)d_in[8];
    const float* gcb     = (const float*)d_in[9];
    const float* gcm     = (const float*)d_in[10];
    const float* gcv     = (const float*)d_in[11];
    const float* bng     = (const float*)d_in[12];
    const float* bnb     = (const float*)d_in[13];
    const float* bnm     = (const float*)d_in[14];
    const float* bnv     = (const float*)d_in[15];
    const float* obg     = (const float*)d_in[16];
    const float* obb     = (const float*)d_in[17];
    const float* obm     = (const float*)d_in[18];
    const float* obv     = (const float*)d_in[19];
    float* out = (float*)d_out;

    k_mega<<<GRID, 256>>>(x, adj, W_start, b_start, W_skip, b_skip, W_gc, b_gc,
                          gcg, gcb, gcm, gcv, bng, bnb, bnm, bnv,
                          obg, obb, obm, obv, out);
    (void)in_sizes; (void)n_in; (void)out_size;
}

// round 17
// speedup vs baseline: 1.4894x; 1.4894x over previous
#include <cuda_runtime.h>
#include <math.h>

#define GRID 296
#define TT 12
#define DD 128
#define NPL (1536 * 512)
#define MSZ (512 * 512)
#define EPSBN 1e-5f

__device__ __align__(16) float g_Y0[NPL];
__device__ __align__(16) float g_Ys[2 * NPL];     // solid Y1, Y2
__device__ __align__(16) float g_Hp[6 * NPL];     // 3 K-parts x 2 planes
__device__ __align__(16) float g_A2[MSZ];
__device__ __align__(16) float g_A2p[4 * MSZ];    // A^2 K-quarter partials
__device__ __align__(16) float g_q[5 * 512];
__device__ float g_Sfin[10 * DD];
__device__ float g_SkUf[DD * 5];
__device__ float g_mo[DD];
__device__ unsigned g_bcnt = 0u;
__device__ unsigned g_bgen = 0u;

__device__ __forceinline__ void grid_sync() {
    __threadfence();
    __syncthreads();
    if (threadIdx.x == 0) {
        unsigned gen = atomicAdd(&g_bgen, 0u);
        if (atomicAdd(&g_bcnt, 1u) == (unsigned)GRID - 1u) {
            atomicExch(&g_bcnt, 0u);
            __threadfence();
            atomicAdd(&g_bgen, 1u);
        } else {
            while (atomicAdd(&g_bgen, 0u) == gen) __nanosleep(128);
        }
        __threadfence();
    }
    __syncthreads();
}

// ---- 128x128 SGEMM tile, 8x8/thread, DOUBLE-buffered smem, plain FFMA ----
__device__ __forceinline__ void sgemm128(float* SMb,
    const float* __restrict__ A, const float* __restrict__ B, float* __restrict__ C,
    int m0, int n0, int k0, int nkt)
{
    // buffers: As[2][16][128], Bs[2][16][128]  (4*2048 floats = 32 KB)
    float (*As)[16][128] = (float(*)[16][128])SMb;
    float (*Bs)[16][128] = (float(*)[16][128])(SMb + 4096);
    int tid = threadIdx.x;
    int tx = tid & 15, ty = tid >> 4;
    int ar0 = tid >> 1, ak0 = (tid & 1) << 3;
    const float* Ap = A + (size_t)(m0 + ar0) * 512 + k0 + ak0;
    int bk = tid >> 5, bc = (tid & 31) << 2;
    const float* Bp0 = B + (size_t)(k0 + bk) * 512 + n0 + bc;
    const float* Bp1 = Bp0 + (size_t)8 * 512;

    float4 a0 = *(const float4*)Ap;
    float4 a1 = *(const float4*)(Ap + 4);
    float4 b0 = *(const float4*)Bp0;
    float4 b1 = *(const float4*)Bp1;
    As[0][ak0 + 0][ar0] = a0.x; As[0][ak0 + 1][ar0] = a0.y;
    As[0][ak0 + 2][ar0] = a0.z; As[0][ak0 + 3][ar0] = a0.w;
    As[0][ak0 + 4][ar0] = a1.x; As[0][ak0 + 5][ar0] = a1.y;
    As[0][ak0 + 6][ar0] = a1.z; As[0][ak0 + 7][ar0] = a1.w;
    *(float4*)&Bs[0][bk][bc] = b0;
    *(float4*)&Bs[0][bk + 8][bc] = b1;
    __syncthreads();

    float acc[8][8];
#pragma unroll
    for (int i = 0; i < 8; i++)
#pragma unroll
        for (int j = 0; j < 8; j++) acc[i][j] = 0.f;

#pragma unroll 1
    for (int kt = 0; kt < nkt; kt++) {
        int cur = kt & 1;
        if (kt + 1 < nkt) {
            a0 = *(const float4*)(Ap + (kt + 1) * 16);
            a1 = *(const float4*)(Ap + (kt + 1) * 16 + 4);
            b0 = *(const float4*)(Bp0 + (size_t)(kt + 1) * 16 * 512);
            b1 = *(const float4*)(Bp1 + (size_t)(kt + 1) * 16 * 512);
        }
#pragma unroll
        for (int k = 0; k < 16; k++) {
            float a[8], b[8];
            *(float4*)&a[0] = *(const float4*)&As[cur][k][ty * 8];
            *(float4*)&a[4] = *(const float4*)&As[cur][k][ty * 8 + 4];
            *(float4*)&b[0] = *(const float4*)&Bs[cur][k][tx * 8];
            *(float4*)&b[4] = *(const float4*)&Bs[cur][k][tx * 8 + 4];
#pragma unroll
            for (int i = 0; i < 8; i++)
#pragma unroll
                for (int j = 0; j < 8; j++) acc[i][j] += a[i] * b[j];
        }
        if (kt + 1 < nkt) {
            int nx = cur ^ 1;
            As[nx][ak0 + 0][ar0] = a0.x; As[nx][ak0 + 1][ar0] = a0.y;
            As[nx][ak0 + 2][ar0] = a0.z; As[nx][ak0 + 3][ar0] = a0.w;
            As[nx][ak0 + 4][ar0] = a1.x; As[nx][ak0 + 5][ar0] = a1.y;
            As[nx][ak0 + 6][ar0] = a1.z; As[nx][ak0 + 7][ar0] = a1.w;
            *(float4*)&Bs[nx][bk][bc] = b0;
            *(float4*)&Bs[nx][bk + 8][bc] = b1;
            __syncthreads();
        }
    }
#pragma unroll
    for (int i = 0; i < 8; i++) {
        float* cp = C + (size_t)(m0 + ty * 8 + i) * 512 + n0 + tx * 8;
        *(float4*)cp = make_float4(acc[i][0], acc[i][1], acc[i][2], acc[i][3]);
        *(float4*)(cp + 4) = make_float4(acc[i][4], acc[i][5], acc[i][6], acc[i][7]);
    }
}

// ------------- colsum / vecmat (64 cols per task) -------------
__device__ void colsum_task(float* SMf, const float* __restrict__ M, float* dst, int blk) {
    int tid = threadIdx.x;
    int col = blk * 64 + (tid & 63);
    int rs = tid >> 6;
    float a = 0.f;
#pragma unroll 8
    for (int v = rs * 128; v < rs * 128 + 128; v++) a += M[(size_t)v * 512 + col];
    SMf[tid] = a;
    __syncthreads();
    if (rs == 0)
        dst[col] = SMf[tid] + SMf[tid + 64] + SMf[tid + 128] + SMf[tid + 192];
}
__device__ void vecmat_task(float* SMf, const float* __restrict__ qsrc,
                            const float* __restrict__ M, float* dst, int blk) {
    int tid = threadIdx.x;
    for (int i = tid; i < 512; i += 256) SMf[i] = qsrc[i];
    __syncthreads();
    int col = blk * 64 + (tid & 63);
    int rs = tid >> 6;
    float a = 0.f;
#pragma unroll 8
    for (int v = rs * 128; v < rs * 128 + 128; v++) a += SMf[v] * M[(size_t)v * 512 + col];
    SMf[512 + tid] = a;
    __syncthreads();
    if (rs == 0)
        dst[col] = SMf[512 + tid] + SMf[512 + tid + 64]
                 + SMf[512 + tid + 128] + SMf[512 + tid + 192];
}

// ------------- warp-cooperative composite chain ---------
__device__ void composite_run(float* SM,
    const float* __restrict__ W_start, const float* __restrict__ b_start,
    const float* __restrict__ W_skip,  const float* __restrict__ b_skip,
    const float* __restrict__ W_gc,    const float* __restrict__ b_gc,
    const float* __restrict__ gcg, const float* __restrict__ gcb,
    const float* __restrict__ gcm, const float* __restrict__ gcv,
    const float* __restrict__ bng, const float* __restrict__ bnb,
    const float* __restrict__ bnm, const float* __restrict__ bnv,
    const float* __restrict__ obg, const float* __restrict__ obb,
    const float* __restrict__ obm, const float* __restrict__ obv)
{
    float* Sg  = SM;
    float* Ca  = SM + 5760;
    float* Ua  = Ca + 1280;
    float* SkC = Ua + 640;
    float* SkU = SkC + 1280;
    int tid = threadIdx.x, wid = tid >> 5, lane = tid & 31;

    for (int i = tid; i < 1280; i += 256) { Ca[i] = 0.f; SkC[i] = 0.f; }
    for (int i = tid; i < 640;  i += 256) { Ua[i] = 0.f; SkU[i] = 0.f; }
    __syncthreads();
    if (tid < 128) {
        Ca[tid * 2 + 0] = W_start[tid * 2 + 0];
        Ca[tid * 2 + 1] = W_start[tid * 2 + 1];
        Ua[tid * 5] = b_start[tid];
    }
    __syncthreads();
    for (int s = 0; s < 5; s++) {
        int i = s >> 1, isgc = s & 1;
        int jmax = isgc ? 384 : 128;
        for (int j = tid; j < jmax; j += 256) {
            int sub = j >> 7, m = j & 127;
#pragma unroll
            for (int v = 0; v < 10; v++) {
                int p = (v >> 1) - sub;
                Sg[j * 15 + v] = (p >= 0) ? Ca[p * 256 + m * 2 + (v & 1)] : 0.f;
            }
#pragma unroll
            for (int k = 0; k < 5; k++) {
                int kk = k - sub;
                Sg[j * 15 + 10 + k] = (kk >= 0) ? Ua[m * 5 + kk] : 0.f;
            }
        }
        __syncthreads();
        const float* Wb = isgc ? (W_gc + i * 128 * 384) : (W_skip + i * 128 * 128);
        for (int ci = 0; ci < 16; ci++) {
            int c = wid * 16 + ci;
            const float* Wr = Wb + (size_t)c * jmax;
            float acc[15];
#pragma unroll
            for (int v = 0; v < 15; v++) acc[v] = 0.f;
            int nu = isgc ? 12 : 4;
            for (int u = 0; u < nu; u++) {
                float w = Wr[lane + u * 32];
                const float* sp = &Sg[(lane + u * 32) * 15];
#pragma unroll
                for (int v = 0; v < 15; v++) acc[v] += w * sp[v];
            }
            float mine = 0.f;
#pragma unroll
            for (int v = 0; v < 15; v++) {
                float r = acc[v];
#pragma unroll
                for (int o = 16; o; o >>= 1) r += __shfl_xor_sync(0xffffffffu, r, o);
                if (lane == v) mine = r;
            }
            if (!isgc) {
                if (lane < 10) SkC[(lane >> 1) * 256 + c * 2 + (lane & 1)] += mine;
                else if (lane < 15) {
                    int kk = lane - 10;
                    SkU[c * 5 + kk] += mine + ((kk == 0) ? b_skip[i * 128 + c] : 0.f);
                }
            } else if (lane < 15) {
                float ig = gcg[i * 128 + c] * rsqrtf(gcv[i * 128 + c] + EPSBN);
                float mg = gcb[i * 128 + c] - gcm[i * 128 + c] * ig;
                float ib = bng[i * 128 + c] * rsqrtf(bnv[i * 128 + c] + EPSBN);
                float mb = bnb[i * 128 + c] - bnm[i * 128 + c] * ib;
                if (lane < 10) {
                    int p = lane >> 1, e = lane & 1, id = p * 256 + c * 2 + e;
                    Ca[id] = ib * (ig * mine + Ca[id]);
                } else {
                    int kk = lane - 10, id = c * 5 + kk;
                    float h = mine + ((kk == 0) ? b_gc[i * 128 + c] : 0.f);
                    Ua[id] = ib * (ig * h + ((kk == 0) ? mg : 0.f) + Ua[id])
                           + ((kk == 0) ? mb : 0.f);
                }
            }
        }
        __syncthreads();
    }
    if (tid < 128) {
        int c = tid;
        float io = obg[c] * rsqrtf(obv[c] + EPSBN);
#pragma unroll
        for (int v = 0; v < 10; v++)
            g_Sfin[v * 128 + c] = io * SkC[(v >> 1) * 256 + c * 2 + (v & 1)];
#pragma unroll
        for (int k = 0; k < 5; k++) g_SkUf[c * 5 + k] = io * SkU[c * 5 + k];
        g_mo[c] = obb[c] - obm[c] * io;
    }
}

// ---------------- the single persistent kernel ----------------
__global__ void __launch_bounds__(256, 2) k_mega(
    const float* __restrict__ x, const float* __restrict__ adj,
    const float* __restrict__ W_start, const float* __restrict__ b_start,
    const float* __restrict__ W_skip,  const float* __restrict__ b_skip,
    const float* __restrict__ W_gc,    const float* __restrict__ b_gc,
    const float* __restrict__ gcg, const float* __restrict__ gcb,
    const float* __restrict__ gcm, const float* __restrict__ gcv,
    const float* __restrict__ bng, const float* __restrict__ bnb,
    const float* __restrict__ bnm, const float* __restrict__ bnv,
    const float* __restrict__ obg, const float* __restrict__ obb,
    const float* __restrict__ obm, const float* __restrict__ obv,
    float* __restrict__ out)
{
    __shared__ __align__(16) float SM[9600];
    int bid = blockIdx.x, tid = threadIdx.x;

    // ===== P0: transpose(128) | A^2 K-quarters(64) | q1(8) | composite(1) ====
    for (int t = bid; t < 201; t += GRID) {
        __syncthreads();
        if (t < 128) {
            const float* src = x + (size_t)t * 6144;
            for (int i = tid; i < 6144; i += 256) SM[i] = src[i];
            __syncthreads();
            float* dst = g_Y0 + (size_t)t * 6144;
            for (int i = tid; i < 6144; i += 256) {
                int tt = i >> 9, n = i & 511;
                dst[i] = SM[n * TT + tt];
            }
        } else if (t < 192) {
            int ti = t - 128, kh = ti >> 4, tile = ti & 15;
            sgemm128(SM, adj, adj, g_A2p + (size_t)kh * MSZ,
                     (tile >> 2) * 128, (tile & 3) * 128, kh * 128, 8);
        } else if (t < 200) {
            colsum_task(SM, adj, g_q + 512, t - 192);
        } else {
            composite_run(SM, W_start, b_start, W_skip, b_skip, W_gc, b_gc,
                          gcg, gcb, gcm, gcv, bng, bnb, bnm, bnv,
                          obg, obb, obm, obv);
        }
    }
    grid_sync();

    // ===== P0b: solidify A^2 (16 tasks) =====
    for (int t = bid; t < 16; t += GRID) {
        const float4* pa = (const float4*)g_A2p + (size_t)t * 4096;
        const float4* pb = pa + MSZ / 4;
        const float4* pc = pb + MSZ / 4;
        const float4* pe = pc + MSZ / 4;
        float4* pd = (float4*)g_A2 + (size_t)t * 4096;
        for (int i = tid; i < 4096; i += 256) {
            float4 a = pa[i], b = pb[i], c = pc[i], e = pe[i];
            pd[i] = make_float4(a.x + b.x + c.x + e.x, a.y + b.y + c.y + e.y,
                                a.z + b.z + c.z + e.z, a.w + b.w + c.w + e.w);
        }
    }
    grid_sync();

    // ===== P1: Y1 thirds(144) | Y2 thirds(144) | q2(8) = 296 =====
    for (int t = bid; t < 296; t += GRID) {
        __syncthreads();
        if (t < 288) {
            int plane = t / 144, r = t % 144;
            int kh = r / 48, rr = r % 48;
            sgemm128(SM, g_Y0, plane ? g_A2 : adj,
                     g_Hp + (size_t)kh * (2 * NPL) + (size_t)plane * NPL,
                     (rr >> 2) * 128, (rr & 3) * 128, kh * 176, (kh == 2) ? 10 : 11);
        } else {
            colsum_task(SM, g_A2, g_q + 1024, t - 288);
        }
    }
    grid_sync();

    // ===== P1b: solidify Y1,Y2 (48) | q3(8) | q4(8) = 64 =====
    for (int t = bid; t < 64; t += GRID) {
        __syncthreads();
        if (t < 48) {
            const float4* p0 = (const float4*)g_Hp + (size_t)t * 8192;
            const float4* p1 = p0 + (2 * NPL) / 4;
            const float4* p2 = p1 + (2 * NPL) / 4;
            float4* pd = (float4*)g_Ys + (size_t)t * 8192;
            for (int i = tid; i < 8192; i += 256) {
                float4 a = p0[i], b = p1[i], c = p2[i];
                pd[i] = make_float4(a.x + b.x + c.x, a.y + b.y + c.y,
                                    a.z + b.z + c.z, a.w + b.w + c.w);
            }
        } else if (t < 56) {
            vecmat_task(SM, g_q + 512, g_A2, g_q + 1536, t - 48);
        } else {
            vecmat_task(SM, g_q + 1024, g_A2, g_q + 2048, t - 56);
        }
    }
    grid_sync();

    // ===== P2: Y3 thirds(144) | Y4 thirds(144) = 288 =====
    for (int t = bid; t < 288; t += GRID) {
        __syncthreads();
        int plane = t / 144, r = t % 144;
        int kh = r / 48, rr = r % 48;
        sgemm128(SM, g_Ys + (size_t)plane * NPL, g_A2,
                 g_Hp + (size_t)kh * (2 * NPL) + (size_t)plane * NPL,
                 (rr >> 2) * 128, (rr & 3) * 128, kh * 176, (kh == 2) ? 10 : 11);
    }
    grid_sync();

    // ===== P3: final expansion (12288 tiles of 32 nodes) =====
    {
        float* S    = SM;            // 1280
        float* SkUs = SM + 1280;     // 640
        float* mos  = SM + 1920;     // 128
        float* qs   = SM + 2048;     // 2048
        for (int i = tid; i < 1280; i += 256) S[i] = g_Sfin[i];
        for (int i = tid; i < 640;  i += 256) SkUs[i] = g_SkUf[i];
        if (tid < 128) mos[tid] = g_mo[tid];
        for (int i = tid; i < 2048; i += 256) qs[i] = g_q[512 + i];
        __syncthreads();
        int i = tid >> 3, c0 = (tid & 7) * 16;
        for (int task = bid; task < 12288; task += GRID) {
            int nt = task & 15, bt = task >> 4;
            int b = bt / TT, tt = bt - b * TT;
            int n = nt * 32 + i;
            size_t ro = (size_t)((b * 2) * TT + tt) * 512 + n;
            size_t r1 = ro + (size_t)TT * 512;
            float y[10];
            y[0] = g_Y0[ro]; y[1] = g_Y0[r1];
            y[2] = g_Ys[ro]; y[3] = g_Ys[r1];
            y[4] = g_Ys[NPL + ro]; y[5] = g_Ys[NPL + r1];
            y[6] = g_Hp[ro] + g_Hp[2 * NPL + ro] + g_Hp[4 * NPL + ro];
            y[7] = g_Hp[r1] + g_Hp[2 * NPL + r1] + g_Hp[4 * NPL + r1];
            y[8] = g_Hp[NPL + ro] + g_Hp[3 * NPL + ro] + g_Hp[5 * NPL + ro];
            y[9] = g_Hp[NPL + r1] + g_Hp[3 * NPL + r1] + g_Hp[5 * NPL + r1];
            float q1 = qs[n], q2 = qs[512 + n], q3 = qs[1024 + n], q4 = qs[1536 + n];
            float acc[16];
#pragma unroll
            for (int cc = 0; cc < 16; cc++) {
                int c = c0 + cc;
                acc[cc] = mos[c] + SkUs[c * 5 + 0] + SkUs[c * 5 + 1] * q1
                        + SkUs[c * 5 + 2] * q2 + SkUs[c * 5 + 3] * q3
                        + SkUs[c * 5 + 4] * q4;
            }
#pragma unroll
            for (int j = 0; j < 10; j++) {
                float yj = y[j];
#pragma unroll
                for (int cc = 0; cc < 16; cc++) acc[cc] += yj * S[j * 128 + c0 + cc];
            }
            float* op = out + (size_t)(bt * 512 + n) * 128 + c0;
#pragma unroll
            for (int q4i = 0; q4i < 4; q4i++)
                *(float4*)(op + q4i * 4) = make_float4(acc[q4i * 4], acc[q4i * 4 + 1],
                                                       acc[q4i * 4 + 2], acc[q4i * 4 + 3]);
        }
    }
}

extern "C" void kernel_launch(void* const* d_in, const int* in_sizes, int n_in,
                              void* d_out, int out_size) {
    const float* x       = (const float*)d_in[0];
    const float* adj     = (const float*)d_in[1];
    const float* W_start = (const float*)d_in[2];
    const float* b_start = (const float*)d_in[3];
    const float* W_skip  = (const float*)d_in[4];
    const float* b_skip  = (const float*)d_in[5];
    const float* W_gc    = (const float*)d_in[6];
    const float* b_gc    = (const float*)d_in[7];
    const float* gcg     = (const float*)d_in[8];
    const float* gcb     = (const float*)d_in[9];
    const float* gcm     = (const float*)d_in[10];
    const float* gcv     = (const float*)d_in[11];
    const float* bng     = (const float*)d_in[12];
    const float* bnb     = (const float*)d_in[13];
    const float* bnm     = (const float*)d_in[14];
    const float* bnv     = (const float*)d_in[15];
    const float* obg     = (const float*)d_in[16];
    const float* obb     = (const float*)d_in[17];
    const float* obm     = (const float*)d_in[18];
    const float* obv     = (const float*)d_in[19];
    float* out = (float*)d_out;

    k_mega<<<GRID, 256>>>(x, adj, W_start, b_start, W_skip, b_skip, W_gc, b_gc,
                          gcg, gcb, gcm, gcv, bng, bnb, bnm, bnv,
                          obg, obb, obm, obv, out);
    (void)in_sizes; (void)n_in; (void)out_size;
}